// round 2
// baseline (speedup 1.0000x reference)
#include <cuda_runtime.h>
#include <cuda_bf16.h>

#define FULL 0xFFFFFFFFu
typedef unsigned long long ull;

// Per-gate Ry part: (cos(theta/2), sin(theta/2))
__device__ float2 g_ry[32];
// Per-gate Euler phase angles lambda, phi
__device__ float g_lam[32];
__device__ float g_phi[32];
// Diagonal phase tables D0..D3: 4 x 256 complex (cos, sin)
__device__ float2 g_diag[4 * 256];

// Relabeled parity rows per gate (must match template R args below)
__constant__ int c_rows[32] = {
    0x80,0x40,0x20,0x10,0x08,0x04,0x02,0x01,
    0x80,0xC0,0xE0,0xF0,0xF8,0xFC,0xFE,0xFF,
    0x80,0x40,0xA0,0x50,0xA8,0x54,0xAA,0x55,
    0x80,0xC0,0x60,0x30,0x98,0xCC,0x66,0x33
};

// ---- prep 1: fuse Rz*Ry*Rx per gate, then ZYZ Euler decomposition ----
__global__ void prep_gates(const float* __restrict__ w) {
    int g = threadIdx.x;
    if (g >= 32) return;
    int base = g * 3;
    float ta = w[base]     * 0.5f;
    float tb = w[base + 1] * 0.5f;
    float tc = w[base + 2] * 0.5f;
    float sa = sinf(ta), ca = cosf(ta);
    float sb = sinf(tb), cb = cosf(tb);
    float sc = sinf(tc), cc = cosf(tc);
    // M = Ry*Rx: m00 = cb*ca + i sb*sa ; m01 = -sb*ca - i cb*sa
    float m00r = cb * ca, m00i = sb * sa;
    float m01r = -sb * ca, m01i = -cb * sa;
    // u0j = (cc - i sc) * m0j
    float x = cc * m00r + sc * m00i;   // u00r
    float y = cc * m00i - sc * m00r;   // u00i
    float z = cc * m01r + sc * m01i;   // u01r
    float q = cc * m01i - sc * m01r;   // u01i
    // ZYZ: u00 = ct*e^{-ia}, u01 = -st*e^{-ib}; a=(phi+lam)/2, b=(phi-lam)/2
    float ct = sqrtf(x * x + y * y);
    float st = sqrtf(z * z + q * q);
    float a = -atan2f(y, x);          // atan2(0,0)=0 is fine (theta=pi case)
    float b = atan2f(q, -z);          // fine when st=0 (theta=0 case)
    g_ry[g] = make_float2(ct, st);
    g_lam[g] = a - b;
    g_phi[g] = a + b;
}

// ---- prep 2: build diagonal tables ----
// Phase for slot s: role(s)=<row,s> mod 2; role 1 -> +alpha/2, role 0 -> -alpha/2
__global__ void prep_diag() {
    int s = threadIdx.x;
    if (s >= 256) return;
#pragma unroll
    for (int j = 0; j < 4; j++) {
        float th = 0.f;
        if (j == 0) {
            for (int g = 0; g < 8; g++) {
                float sg = (__popc(c_rows[g] & s) & 1) ? 1.f : -1.f;
                th += 0.5f * g_lam[g] * sg;
            }
        } else {
            for (int g = 8 * (j - 1); g < 8 * (j - 1) + 8; g++) {
                float sg = (__popc(c_rows[g] & s) & 1) ? 1.f : -1.f;
                th += 0.5f * g_phi[g] * sg;
            }
            for (int g = 8 * j; g < 8 * j + 8; g++) {
                float sg = (__popc(c_rows[g] & s) & 1) ? 1.f : -1.f;
                th += 0.5f * g_lam[g] * sg;
            }
        }
        float cs, sn;
        sincosf(th, &sn, &cs);
        g_diag[j * 256 + s] = make_float2(cs, sn);
    }
}

// ---- packed fp32x2 helpers ----
__device__ __forceinline__ ull fma2(ull a, ull b, ull c) {
    ull d; asm("fma.rn.f32x2 %0, %1, %2, %3;" : "=l"(d) : "l"(a), "l"(b), "l"(c));
    return d;
}
__device__ __forceinline__ ull mul2(ull a, ull b) {
    ull d; asm("mul.rn.f32x2 %0, %1, %2;" : "=l"(d) : "l"(a), "l"(b));
    return d;
}
__device__ __forceinline__ ull pack2(float lo, float hi) {
    ull d; asm("mov.b64 %0, {%1, %2};" : "=l"(d) : "f"(lo), "f"(hi));
    return d;
}
__device__ __forceinline__ float lo32(ull v) { return __uint_as_float((unsigned)v); }
__device__ __forceinline__ float hi32(ull v) { return __uint_as_float((unsigned)(v >> 32)); }

// ---- Ry gate: slot pair mask M, parity row R, gate index G ----
// new[s] = c*a[s] + sigma(s)*st*a[s^M], sigma = +1 if <R,s> odd else -1.
template<int M, int R, int G>
__device__ __forceinline__ void rygate(ull (&v)[8], int lane) {
    const float2 cs = g_ry[G];
    constexpr int ML = (M >> 3) & 31;
    constexpr int MK = M & 7;
    constexpr int RL = (R >> 3) & 31;
    constexpr int RK = R & 7;

    int pl = __popc(lane & RL) & 1;
    float sA = pl ? cs.y : -cs.y;     // sign for k-parity-even slots
    ull c2 = pack2(cs.x, cs.x);
    ull sP = pack2(sA, sA);
    ull sN = pack2(-sA, -sA);

    ull b[8];
#pragma unroll
    for (int k = 0; k < 8; k++) {
        if constexpr (ML != 0)
            b[k] = __shfl_xor_sync(FULL, v[k ^ MK], ML);
        else
            b[k] = v[k ^ MK];
    }
#pragma unroll
    for (int k = 0; k < 8; k++) {
        const bool odd = ((0x96 >> (RK & k)) & 1) != 0;  // parity(RK & k)
        v[k] = fma2(odd ? sN : sP, b[k], mul2(c2, v[k]));
    }
}

__device__ __forceinline__ void applyD(ull (&v)[8], int base, int j) {
    const float2* t = g_diag + j * 256 + base;
#pragma unroll
    for (int k = 0; k < 8; k++) {
        float2 p = t[k];
        float ar = lo32(v[k]), ai = hi32(v[k]);
        float nr = p.x * ar - p.y * ai;
        float ni = p.x * ai + p.y * ar;
        v[k] = pack2(nr, ni);
    }
}

__global__ void __launch_bounds__(256)
qsim(const float* __restrict__ x, float* __restrict__ out, int B) {
    int warp = (blockIdx.x * blockDim.x + threadIdx.x) >> 5;
    int lane = threadIdx.x & 31;
    if (warp >= B) return;
    int base = lane * 8;  // this thread's first slot index

    // ---- encoding: product state (all-real), then fold in D0 ----
    float xq = x[warp * 8 + (lane & 7)];
    float sh, ch;
    __sincosf(0.5f * xq, &sh, &ch);
    float c[8], s[8];
#pragma unroll
    for (int q = 0; q < 8; q++) {
        c[q] = __shfl_sync(FULL, ch, q);
        s[q] = __shfl_sync(FULL, sh, q);
    }
    float lp = 1.f;
#pragma unroll
    for (int q = 0; q < 5; q++)
        lp *= ((lane >> (4 - q)) & 1) ? s[q] : c[q];

    ull v[8];
#pragma unroll
    for (int k = 0; k < 8; k++) {
        float amp = lp * (((k >> 2) & 1) ? s[5] : c[5]) *
                         (((k >> 1) & 1) ? s[6] : c[6]) *
                         (((k)      & 1) ? s[7] : c[7]);
        float2 p0 = g_diag[base + k];   // D0 table (j=0)
        v[k] = pack2(amp * p0.x, amp * p0.y);
    }

    // ---- RyBlock layer 1 ----
    rygate<0x80, 0x80,  0>(v, lane);
    rygate<0x40, 0x40,  1>(v, lane);
    rygate<0x20, 0x20,  2>(v, lane);
    rygate<0x10, 0x10,  3>(v, lane);
    rygate<0x08, 0x08,  4>(v, lane);
    rygate<0x04, 0x04,  5>(v, lane);
    rygate<0x02, 0x02,  6>(v, lane);
    rygate<0x01, 0x01,  7>(v, lane);
    applyD(v, base, 1);
    // ---- layer 2 ----
    rygate<0xC0, 0x80,  8>(v, lane);
    rygate<0x60, 0xC0,  9>(v, lane);
    rygate<0x30, 0xE0, 10>(v, lane);
    rygate<0x18, 0xF0, 11>(v, lane);
    rygate<0x0C, 0xF8, 12>(v, lane);
    rygate<0x06, 0xFC, 13>(v, lane);
    rygate<0x03, 0xFE, 14>(v, lane);
    rygate<0x01, 0xFF, 15>(v, lane);
    applyD(v, base, 2);
    // ---- layer 3 ----
    rygate<0xA0, 0x80, 16>(v, lane);
    rygate<0x50, 0x40, 17>(v, lane);
    rygate<0x28, 0xA0, 18>(v, lane);
    rygate<0x14, 0x50, 19>(v, lane);
    rygate<0x0A, 0xA8, 20>(v, lane);
    rygate<0x05, 0x54, 21>(v, lane);
    rygate<0x02, 0xAA, 22>(v, lane);
    rygate<0x01, 0x55, 23>(v, lane);
    applyD(v, base, 3);
    // ---- layer 4 (trailing diagonal D4 dropped: |amp|^2 invariant) ----
    rygate<0xF0, 0x80, 24>(v, lane);
    rygate<0x78, 0xC0, 25>(v, lane);
    rygate<0x3C, 0x60, 26>(v, lane);
    rygate<0x1E, 0x30, 27>(v, lane);
    rygate<0x0F, 0x98, 28>(v, lane);
    rygate<0x07, 0xCC, 29>(v, lane);
    rygate<0x03, 0x66, 30>(v, lane);
    rygate<0x01, 0x33, 31>(v, lane);

    // ---- measurement: <Z_q> with final relabeling rows
    // rows: q0:0x80 q1:0x40 q2:0x20 q3:0x10 q4:0x88 q5:0x44 q6:0x22 q7:0x11
    float P = 0.f, D2 = 0.f, D1 = 0.f, D0 = 0.f;
#pragma unroll
    for (int k = 0; k < 8; k++) {
        float ar = lo32(v[k]), ai = hi32(v[k]);
        float p = ar * ar + ai * ai;
        P += p;
        D2 += (k & 4) ? -p : p;
        D1 += (k & 2) ? -p : p;
        D0 += (k & 1) ? -p : p;
    }
    float z[8];
    z[0] = (lane & 16) ? -P : P;
    z[1] = (lane & 8)  ? -P : P;
    z[2] = (lane & 4)  ? -P : P;
    z[3] = (lane & 2)  ? -P : P;
    z[4] = (__popc(lane & 0x11) & 1) ? -P : P;
    z[5] = (lane & 8)  ? -D2 : D2;
    z[6] = (lane & 4)  ? -D1 : D1;
    z[7] = (lane & 2)  ? -D0 : D0;

#pragma unroll
    for (int off = 16; off >= 1; off >>= 1) {
#pragma unroll
        for (int i = 0; i < 8; i++)
            z[i] += __shfl_xor_sync(FULL, z[i], off);
    }
    if (lane == 0) {
        float4* o = (float4*)(out + warp * 8);
        o[0] = make_float4(z[0], z[1], z[2], z[3]);
        o[1] = make_float4(z[4], z[5], z[6], z[7]);
    }
}

extern "C" void kernel_launch(void* const* d_in, const int* in_sizes, int n_in,
                              void* d_out, int out_size) {
    const float* x = (const float*)d_in[0];
    const float* w = (const float*)d_in[1];
    float* out = (float*)d_out;
    int B = in_sizes[0] / 8;

    prep_gates<<<1, 32>>>(w);
    prep_diag<<<1, 256>>>();

    int threads = 256;
    long long total = (long long)B * 32;
    int blocks = (int)((total + threads - 1) / threads);
    qsim<<<blocks, threads>>>(x, out, B);
}

// round 3
// speedup vs baseline: 1.0336x; 1.0336x over previous
#include <cuda_runtime.h>
#include <cuda_bf16.h>

#define FULL 0xFFFFFFFFu
typedef unsigned long long ull;

// Per-gate Ry part: (cos(theta/2), sin(theta/2))
__device__ float2 g_ry[32];
// Diagonal phase tables D0..D3: 4 x 256 complex (cos, sin)
__device__ float2 g_diag[4 * 256];

// Relabeled parity rows per gate (must match template R args below)
__constant__ int c_rows[32] = {
    0x80,0x40,0x20,0x10,0x08,0x04,0x02,0x01,
    0x80,0xC0,0xE0,0xF0,0xF8,0xFC,0xFE,0xFF,
    0x80,0x40,0xA0,0x50,0xA8,0x54,0xAA,0x55,
    0x80,0xC0,0x60,0x30,0x98,0xCC,0x66,0x33
};

// ---- single fused prep kernel ----
// Threads 0-31: fuse Rz*Ry*Rx -> ZYZ Euler (theta, lambda, phi) into smem.
// Then all 256 threads build the diagonal phase tables.
__global__ void prep(const float* __restrict__ w) {
    __shared__ float s_lam[32], s_phi[32];
    int t = threadIdx.x;
    if (t < 32) {
        int base = t * 3;
        float ta = w[base]     * 0.5f;
        float tb = w[base + 1] * 0.5f;
        float tc = w[base + 2] * 0.5f;
        float sa = sinf(ta), ca = cosf(ta);
        float sb = sinf(tb), cb = cosf(tb);
        float sc = sinf(tc), cc = cosf(tc);
        // M = Ry*Rx: m00 = cb*ca + i sb*sa ; m01 = -sb*ca - i cb*sa
        float m00r = cb * ca, m00i = sb * sa;
        float m01r = -sb * ca, m01i = -cb * sa;
        // u0j = (cc - i sc) * m0j
        float x = cc * m00r + sc * m00i;   // u00r
        float y = cc * m00i - sc * m00r;   // u00i
        float z = cc * m01r + sc * m01i;   // u01r
        float q = cc * m01i - sc * m01r;   // u01i
        // ZYZ: u00 = ct*e^{-ia}, u01 = -st*e^{-ib}; a=(phi+lam)/2, b=(phi-lam)/2
        float ct = sqrtf(x * x + y * y);
        float st = sqrtf(z * z + q * q);
        float a = -atan2f(y, x);
        float b = atan2f(q, -z);
        g_ry[t] = make_float2(ct, st);
        s_lam[t] = a - b;
        s_phi[t] = a + b;
    }
    __syncthreads();

    int s = t;  // slot index 0..255
    float th[4] = {0.f, 0.f, 0.f, 0.f};
#pragma unroll
    for (int g = 0; g < 32; g++) {
        float sg = (__popc(c_rows[g] & s) & 1) ? 1.f : -1.f;
        int L = g >> 3;
        th[L] += 0.5f * s_lam[g] * sg;          // lambda of layer L -> D_L
        if (L < 3) th[L + 1] += 0.5f * s_phi[g] * sg;  // phi -> D_{L+1}; D4 dropped
    }
#pragma unroll
    for (int j = 0; j < 4; j++) {
        float sn, cs;
        sincosf(th[j], &sn, &cs);
        g_diag[j * 256 + s] = make_float2(cs, sn);
    }
}

// ---- packed fp32x2 helpers ----
__device__ __forceinline__ ull fma2(ull a, ull b, ull c) {
    ull d; asm("fma.rn.f32x2 %0, %1, %2, %3;" : "=l"(d) : "l"(a), "l"(b), "l"(c));
    return d;
}
__device__ __forceinline__ ull mul2(ull a, ull b) {
    ull d; asm("mul.rn.f32x2 %0, %1, %2;" : "=l"(d) : "l"(a), "l"(b));
    return d;
}
__device__ __forceinline__ ull pack2(float lo, float hi) {
    ull d; asm("mov.b64 %0, {%1, %2};" : "=l"(d) : "f"(lo), "f"(hi));
    return d;
}
__device__ __forceinline__ ull swap2(ull v) {
    ull d;
    asm("{ .reg .b32 lo, hi; mov.b64 {lo, hi}, %1; mov.b64 %0, {hi, lo}; }"
        : "=l"(d) : "l"(v));
    return d;
}
__device__ __forceinline__ float lo32(ull v) { return __uint_as_float((unsigned)v); }
__device__ __forceinline__ float hi32(ull v) { return __uint_as_float((unsigned)(v >> 32)); }

// ---- Ry gate: slot pair mask M, parity row R, gate index G ----
// new[s] = c*a[s] + sigma(s)*st*a[s^M], sigma = +1 if <R,s> odd else -1.
// In-place pair processing (no staging buffer): both reads of a pair precede
// both writes, and warp lockstep makes remote shuffle reads see old values.
template<int M, int R, int G>
__device__ __forceinline__ void rygate(ull (&v)[8], int lane) {
    const float2 cs = g_ry[G];
    constexpr int ML = (M >> 3) & 31;
    constexpr int MK = M & 7;
    constexpr int RL = (R >> 3) & 31;
    constexpr int RK = R & 7;
    constexpr int HB = (MK >= 4) ? 4 : ((MK >= 2) ? 2 : 1);  // top bit of MK

    int pl = __popc(lane & RL) & 1;
    float sA = pl ? cs.y : -cs.y;
    ull c2 = pack2(cs.x, cs.x);
    ull sP = pack2(sA, sA);
    ull sN = pack2(-sA, -sA);

    if constexpr (MK == 0) {
        // partner in another lane, same local slot: in-place per k
#pragma unroll
        for (int k = 0; k < 8; k++) {
            ull b = __shfl_xor_sync(FULL, v[k], ML);
            const bool odd = ((0x96 >> (RK & k)) & 1) != 0;
            v[k] = fma2(odd ? sN : sP, b, mul2(c2, v[k]));
        }
    } else if constexpr (ML == 0) {
        // purely local pairs (k, k^MK)
#pragma unroll
        for (int k = 0; k < 8; k++) {
            if ((k & HB) == 0) {
                const int k2 = k ^ MK;
                const bool o1 = ((0x96 >> (RK & k )) & 1) != 0;
                const bool o2 = ((0x96 >> (RK & k2)) & 1) != 0;
                ull a = v[k], b = v[k2];
                v[k]  = fma2(o1 ? sN : sP, b, mul2(c2, a));
                v[k2] = fma2(o2 ? sN : sP, a, mul2(c2, b));
            }
        }
    } else {
        // mixed: partner in another lane AND different local slot
#pragma unroll
        for (int k = 0; k < 8; k++) {
            if ((k & HB) == 0) {
                const int k2 = k ^ MK;
                ull b1 = __shfl_xor_sync(FULL, v[k2], ML);
                ull b2 = __shfl_xor_sync(FULL, v[k],  ML);
                const bool o1 = ((0x96 >> (RK & k )) & 1) != 0;
                const bool o2 = ((0x96 >> (RK & k2)) & 1) != 0;
                v[k]  = fma2(o1 ? sN : sP, b1, mul2(c2, v[k]));
                v[k2] = fma2(o2 ? sN : sP, b2, mul2(c2, v[k2]));
            }
        }
    }
}

__device__ __forceinline__ void applyD(ull (&v)[8], int base, int j) {
    const float2* __restrict__ t = g_diag + j * 256 + base;
#pragma unroll
    for (int k = 0; k < 8; k++) {
        float2 p = __ldg(&t[k]);
        // (nr, ni) = (px*ar - py*ai, px*ai + py*ar)
        v[k] = fma2(pack2(p.x, p.x), v[k], mul2(pack2(-p.y, p.y), swap2(v[k])));
    }
}

__global__ void __launch_bounds__(256)
qsim(const float* __restrict__ x, float* __restrict__ out, int B) {
    int warp = (blockIdx.x * blockDim.x + threadIdx.x) >> 5;
    int lane = threadIdx.x & 31;
    if (warp >= B) return;
    int base = lane * 8;  // this thread's first slot index

    // ---- encoding: product state (all-real), then fold in D0 ----
    float xq = x[warp * 8 + (lane & 7)];
    float sh, ch;
    __sincosf(0.5f * xq, &sh, &ch);
    float c[8], s[8];
#pragma unroll
    for (int q = 0; q < 8; q++) {
        c[q] = __shfl_sync(FULL, ch, q);
        s[q] = __shfl_sync(FULL, sh, q);
    }
    float lp = 1.f;
#pragma unroll
    for (int q = 0; q < 5; q++)
        lp *= ((lane >> (4 - q)) & 1) ? s[q] : c[q];

    ull v[8];
#pragma unroll
    for (int k = 0; k < 8; k++) {
        float amp = lp * (((k >> 2) & 1) ? s[5] : c[5]) *
                         (((k >> 1) & 1) ? s[6] : c[6]) *
                         (((k)      & 1) ? s[7] : c[7]);
        float2 p0 = __ldg(&g_diag[base + k]);   // D0 table
        v[k] = pack2(amp * p0.x, amp * p0.y);
    }

    // ---- RyBlock layer 1 ----
    rygate<0x80, 0x80,  0>(v, lane);
    rygate<0x40, 0x40,  1>(v, lane);
    rygate<0x20, 0x20,  2>(v, lane);
    rygate<0x10, 0x10,  3>(v, lane);
    rygate<0x08, 0x08,  4>(v, lane);
    rygate<0x04, 0x04,  5>(v, lane);
    rygate<0x02, 0x02,  6>(v, lane);
    rygate<0x01, 0x01,  7>(v, lane);
    applyD(v, base, 1);
    // ---- layer 2 ----
    rygate<0xC0, 0x80,  8>(v, lane);
    rygate<0x60, 0xC0,  9>(v, lane);
    rygate<0x30, 0xE0, 10>(v, lane);
    rygate<0x18, 0xF0, 11>(v, lane);
    rygate<0x0C, 0xF8, 12>(v, lane);
    rygate<0x06, 0xFC, 13>(v, lane);
    rygate<0x03, 0xFE, 14>(v, lane);
    rygate<0x01, 0xFF, 15>(v, lane);
    applyD(v, base, 2);
    // ---- layer 3 ----
    rygate<0xA0, 0x80, 16>(v, lane);
    rygate<0x50, 0x40, 17>(v, lane);
    rygate<0x28, 0xA0, 18>(v, lane);
    rygate<0x14, 0x50, 19>(v, lane);
    rygate<0x0A, 0xA8, 20>(v, lane);
    rygate<0x05, 0x54, 21>(v, lane);
    rygate<0x02, 0xAA, 22>(v, lane);
    rygate<0x01, 0x55, 23>(v, lane);
    applyD(v, base, 3);
    // ---- layer 4 (trailing diagonal D4 dropped: |amp|^2 invariant) ----
    rygate<0xF0, 0x80, 24>(v, lane);
    rygate<0x78, 0xC0, 25>(v, lane);
    rygate<0x3C, 0x60, 26>(v, lane);
    rygate<0x1E, 0x30, 27>(v, lane);
    rygate<0x0F, 0x98, 28>(v, lane);
    rygate<0x07, 0xCC, 29>(v, lane);
    rygate<0x03, 0x66, 30>(v, lane);
    rygate<0x01, 0x33, 31>(v, lane);

    // ---- measurement: <Z_q> with final relabeling rows
    // rows: q0:0x80 q1:0x40 q2:0x20 q3:0x10 q4:0x88 q5:0x44 q6:0x22 q7:0x11
    float P = 0.f, D2 = 0.f, D1 = 0.f, D0 = 0.f;
#pragma unroll
    for (int k = 0; k < 8; k++) {
        float ar = lo32(v[k]), ai = hi32(v[k]);
        float p = ar * ar + ai * ai;
        P += p;
        D2 += (k & 4) ? -p : p;
        D1 += (k & 2) ? -p : p;
        D0 += (k & 1) ? -p : p;
    }
    float z[8];
    z[0] = (lane & 16) ? -P : P;
    z[1] = (lane & 8)  ? -P : P;
    z[2] = (lane & 4)  ? -P : P;
    z[3] = (lane & 2)  ? -P : P;
    z[4] = (__popc(lane & 0x11) & 1) ? -P : P;
    z[5] = (lane & 8)  ? -D2 : D2;
    z[6] = (lane & 4)  ? -D1 : D1;
    z[7] = (lane & 2)  ? -D0 : D0;

#pragma unroll
    for (int off = 16; off >= 1; off >>= 1) {
#pragma unroll
        for (int i = 0; i < 8; i++)
            z[i] += __shfl_xor_sync(FULL, z[i], off);
    }
    if (lane == 0) {
        float4* o = (float4*)(out + warp * 8);
        o[0] = make_float4(z[0], z[1], z[2], z[3]);
        o[1] = make_float4(z[4], z[5], z[6], z[7]);
    }
}

extern "C" void kernel_launch(void* const* d_in, const int* in_sizes, int n_in,
                              void* d_out, int out_size) {
    const float* x = (const float*)d_in[0];
    const float* w = (const float*)d_in[1];
    float* out = (float*)d_out;
    int B = in_sizes[0] / 8;

    prep<<<1, 256>>>(w);

    int threads = 256;
    long long total = (long long)B * 32;
    int blocks = (int)((total + threads - 1) / threads);
    qsim<<<blocks, threads>>>(x, out, B);
}